// round 6
// baseline (speedup 1.0000x reference)
#include <cuda_runtime.h>
#include <math_constants.h>
#include <stdint.h>

// GlobalAttentionPooling: out[g,:] = sum_{i in seg g} softmax_g(x_i . W + b) * x_i
// N=100000, D=512, G=256. batch is SORTED -> contiguous segments.
//
// batch dtype: the reference asks for int64, but JAX silently downcasts to
// int32 without x64 mode. We detect at runtime: view the buffer as int words;
// words [1,3,...,511] are int64 high-words (all zero, values < 2^31) or
// int32 batch[1..511] (necessarily contains nonzero graph ids for this
// distribution). Binary search then uses element stride 1 or 2.
//
// All 16B vector accesses are alignment-guarded (host check for x/W/out,
// __align__(16) on our own scratch and shared slabs).
//
// Pass 1: one-pass streaming online-softmax. 256 graphs x SPLIT slices,
//         each warp keeps (m, s, acc[16 regs]) and streams full rows.
// Pass 2: merge SPLIT partials per graph, normalize, write out.

#define D_DIM 512
#define G_NUM 256
#define SPLIT 4
#define WPB   8                     // warps per block (pass 1)
#define T_P1  (WPB * 32)            // 256 threads
#define NPART (G_NUM * SPLIT)       // 1024 partials

__device__ __align__(16) float g_part_m[NPART];
__device__ __align__(16) float g_part_s[NPART];
__device__ __align__(16) float g_part_acc[(size_t)NPART * D_DIM];

// lower_bound over batch viewed as int words with given element stride.
__device__ __forceinline__ int lower_bound_batch(const int* __restrict__ a32,
                                                 int n, int v, int stride) {
    int lo = 0, hi = n;
    while (lo < hi) {
        int mid = (lo + hi) >> 1;
        if (a32[mid * stride] < v) lo = mid + 1; else hi = mid;
    }
    return lo;
}

template <bool VEC>
__global__ __launch_bounds__(T_P1)
void gap_pass1(const float* __restrict__ x,
               const float* __restrict__ Wv,
               const float* __restrict__ bv,
               const int* __restrict__ batch32,
               int N)
{
    __shared__ int   sb[2];
    __shared__ int   s_stride;
    __shared__ float sm[WPB];
    __shared__ float ss[WPB];
    __shared__ __align__(16) float sacc[WPB][D_DIM];   // 16 KB merge slab

    const int tid  = threadIdx.x;
    const int w    = tid >> 5;
    const int lane = tid & 31;
    const int g    = blockIdx.x / SPLIT;
    const int j    = blockIdx.x % SPLIT;

    // ---- dtype detection: any nonzero odd word in [1, 512) => int32 ----
    if (tid == 0) s_stride = 2;               // default: int64 (pairs)
    __syncthreads();
    {
        const int idx = 2 * tid + 1;          // 1, 3, ..., 511
        if (idx < N && batch32[idx] != 0) s_stride = 1;   // int32
    }
    __syncthreads();
    const int stride = s_stride;

    if (tid == 0)        sb[0] = lower_bound_batch(batch32, N, g, stride);
    else if (tid == 32)  sb[1] = lower_bound_batch(batch32, N, g + 1, stride);
    __syncthreads();
    const int start = sb[0], end = sb[1];

    const float bias = __ldg(bv);

    float w0x,w0y,w0z,w0w, w1x,w1y,w1z,w1w, w2x,w2y,w2z,w2w, w3x,w3y,w3z,w3w;
    if (VEC) {
        const float4* __restrict__ W4 = (const float4*)Wv;
        float4 t;
        t = W4[lane];      w0x=t.x; w0y=t.y; w0z=t.z; w0w=t.w;
        t = W4[lane + 32]; w1x=t.x; w1y=t.y; w1z=t.z; w1w=t.w;
        t = W4[lane + 64]; w2x=t.x; w2y=t.y; w2z=t.z; w2w=t.w;
        t = W4[lane + 96]; w3x=t.x; w3y=t.y; w3z=t.z; w3w=t.w;
    } else {
        const int c = lane * 4;
        w0x=Wv[c+0];   w0y=Wv[c+1];   w0z=Wv[c+2];   w0w=Wv[c+3];
        w1x=Wv[c+128]; w1y=Wv[c+129]; w1z=Wv[c+130]; w1w=Wv[c+131];
        w2x=Wv[c+256]; w2y=Wv[c+257]; w2z=Wv[c+258]; w2w=Wv[c+259];
        w3x=Wv[c+384]; w3y=Wv[c+385]; w3z=Wv[c+386]; w3w=Wv[c+387];
    }

    float  m = -CUDART_INF_F, s = 0.f;
    float4 a0 = make_float4(0.f,0.f,0.f,0.f);
    float4 a1 = make_float4(0.f,0.f,0.f,0.f);
    float4 a2 = make_float4(0.f,0.f,0.f,0.f);
    float4 a3 = make_float4(0.f,0.f,0.f,0.f);

    for (int r = start + j * WPB + w; r < end; r += SPLIT * WPB) {
        float4 v0, v1, v2, v3;
        if (VEC) {
            const float4* __restrict__ xr = (const float4*)(x + (size_t)r * D_DIM);
            v0 = xr[lane];
            v1 = xr[lane + 32];
            v2 = xr[lane + 64];
            v3 = xr[lane + 96];
        } else {
            const float* __restrict__ xr = x + (size_t)r * D_DIM + lane * 4;
            v0 = make_float4(xr[0],   xr[1],   xr[2],   xr[3]);
            v1 = make_float4(xr[128], xr[129], xr[130], xr[131]);
            v2 = make_float4(xr[256], xr[257], xr[258], xr[259]);
            v3 = make_float4(xr[384], xr[385], xr[386], xr[387]);
        }

        float dot = v0.x * w0x;
        dot = fmaf(v0.y, w0y, dot);
        dot = fmaf(v0.z, w0z, dot);
        dot = fmaf(v0.w, w0w, dot);
        dot = fmaf(v1.x, w1x, dot);
        dot = fmaf(v1.y, w1y, dot);
        dot = fmaf(v1.z, w1z, dot);
        dot = fmaf(v1.w, w1w, dot);
        dot = fmaf(v2.x, w2x, dot);
        dot = fmaf(v2.y, w2y, dot);
        dot = fmaf(v2.z, w2z, dot);
        dot = fmaf(v2.w, w2w, dot);
        dot = fmaf(v3.x, w3x, dot);
        dot = fmaf(v3.y, w3y, dot);
        dot = fmaf(v3.z, w3z, dot);
        dot = fmaf(v3.w, w3w, dot);
        #pragma unroll
        for (int off = 16; off; off >>= 1)
            dot += __shfl_xor_sync(0xffffffffu, dot, off);

        const float gate = dot + bias;
        if (gate <= m) {
            // common path: running max unchanged
            const float p = __expf(gate - m);
            s += p;
            a0.x = fmaf(p, v0.x, a0.x); a0.y = fmaf(p, v0.y, a0.y);
            a0.z = fmaf(p, v0.z, a0.z); a0.w = fmaf(p, v0.w, a0.w);
            a1.x = fmaf(p, v1.x, a1.x); a1.y = fmaf(p, v1.y, a1.y);
            a1.z = fmaf(p, v1.z, a1.z); a1.w = fmaf(p, v1.w, a1.w);
            a2.x = fmaf(p, v2.x, a2.x); a2.y = fmaf(p, v2.y, a2.y);
            a2.z = fmaf(p, v2.z, a2.z); a2.w = fmaf(p, v2.w, a2.w);
            a3.x = fmaf(p, v3.x, a3.x); a3.y = fmaf(p, v3.y, a3.y);
            a3.z = fmaf(p, v3.z, a3.z); a3.w = fmaf(p, v3.w, a3.w);
        } else {
            // new max: rescale state (handles first row via exp(-inf)=0)
            const float c = __expf(m - gate);
            s = fmaf(s, c, 1.0f);
            a0.x = fmaf(a0.x, c, v0.x); a0.y = fmaf(a0.y, c, v0.y);
            a0.z = fmaf(a0.z, c, v0.z); a0.w = fmaf(a0.w, c, v0.w);
            a1.x = fmaf(a1.x, c, v1.x); a1.y = fmaf(a1.y, c, v1.y);
            a1.z = fmaf(a1.z, c, v1.z); a1.w = fmaf(a1.w, c, v1.w);
            a2.x = fmaf(a2.x, c, v2.x); a2.y = fmaf(a2.y, c, v2.y);
            a2.z = fmaf(a2.z, c, v2.z); a2.w = fmaf(a2.w, c, v2.w);
            a3.x = fmaf(a3.x, c, v3.x); a3.y = fmaf(a3.y, c, v3.y);
            a3.z = fmaf(a3.z, c, v3.z); a3.w = fmaf(a3.w, c, v3.w);
            m = gate;
        }
    }

    // ---- merge the 8 warps of this block into one partial ----
    if (lane == 0) { sm[w] = m; ss[w] = s; }
    __syncthreads();

    float M = -CUDART_INF_F;
    #pragma unroll
    for (int k = 0; k < WPB; k++) M = fmaxf(M, sm[k]);

    const float f = (m == -CUDART_INF_F) ? 0.f : __expf(m - M);
    float4* slab = (float4*)&sacc[w][0];   // sacc is __align__(16); rows are 2048 B
    slab[lane]      = make_float4(a0.x*f, a0.y*f, a0.z*f, a0.w*f);
    slab[lane + 32] = make_float4(a1.x*f, a1.y*f, a1.z*f, a1.w*f);
    slab[lane + 64] = make_float4(a2.x*f, a2.y*f, a2.z*f, a2.w*f);
    slab[lane + 96] = make_float4(a3.x*f, a3.y*f, a3.z*f, a3.w*f);
    __syncthreads();

    float bs = 0.f;
    #pragma unroll
    for (int k = 0; k < WPB; k++) {
        const float mk = sm[k];
        const float fk = (mk == -CUDART_INF_F) ? 0.f : __expf(mk - M);
        bs = fmaf(fk, ss[k], bs);
    }

    float o0 = 0.f, o1 = 0.f;
    #pragma unroll
    for (int k = 0; k < WPB; k++) {
        o0 += sacc[k][tid];
        o1 += sacc[k][tid + 256];
    }
    const size_t pb = (size_t)blockIdx.x;
    g_part_acc[pb * D_DIM + tid]       = o0;
    g_part_acc[pb * D_DIM + tid + 256] = o1;
    if (tid == 0) { g_part_m[pb] = M; g_part_s[pb] = bs; }
}

template <bool VECOUT>
__global__ __launch_bounds__(128)
void gap_pass2(float* __restrict__ out)
{
    const int g   = blockIdx.x;
    const int tid = threadIdx.x;
    __shared__ float sf[SPLIT];
    __shared__ float sinv;

    if (tid < 32) {
        // cooperative: lanes 0..SPLIT-1 each load one partial's (m, s)
        float mm  = (tid < SPLIT) ? g_part_m[g * SPLIT + tid] : -CUDART_INF_F;
        float svl = (tid < SPLIT) ? g_part_s[g * SPLIT + tid] : 0.f;
        float M = mm;
        #pragma unroll
        for (int off = 16; off; off >>= 1)
            M = fmaxf(M, __shfl_xor_sync(0xffffffffu, M, off));
        const float fj = (mm == -CUDART_INF_F) ? 0.f : __expf(mm - M);
        float dj = fj * svl;
        #pragma unroll
        for (int off = 16; off; off >>= 1)
            dj += __shfl_xor_sync(0xffffffffu, dj, off);
        if (tid < SPLIT) sf[tid] = fj;
        if (tid == 0)    sinv = (dj > 0.f) ? (1.f / dj) : 0.f;  // empty graph -> zeros
    }
    __syncthreads();

    const float f0 = sf[0], f1 = sf[1], f2 = sf[2], f3 = sf[3];
    const float inv = sinv;
    const float4* __restrict__ p0 = (const float4*)(g_part_acc + (size_t)g * SPLIT * D_DIM);
    const float4* __restrict__ p1 = p0 + (D_DIM / 4);
    const float4* __restrict__ p2 = p0 + 2 * (D_DIM / 4);
    const float4* __restrict__ p3 = p0 + 3 * (D_DIM / 4);

    // 128 threads x float4 = 512 floats: exactly one output row
    const float4 u0 = p0[tid], u1 = p1[tid], u2 = p2[tid], u3 = p3[tid];
    float4 v;
    v.x = (f0*u0.x + f1*u1.x + f2*u2.x + f3*u3.x) * inv;
    v.y = (f0*u0.y + f1*u1.y + f2*u2.y + f3*u3.y) * inv;
    v.z = (f0*u0.z + f1*u1.z + f2*u2.z + f3*u3.z) * inv;
    v.w = (f0*u0.w + f1*u1.w + f2*u2.w + f3*u3.w) * inv;

    if (VECOUT) {
        float4* __restrict__ o4 = (float4*)(out + (size_t)g * D_DIM);
        o4[tid] = v;
    } else {
        float* __restrict__ o = out + (size_t)g * D_DIM + tid * 4;
        o[0] = v.x; o[1] = v.y; o[2] = v.z; o[3] = v.w;
    }
}

extern "C" void kernel_launch(void* const* d_in, const int* in_sizes, int n_in,
                              void* d_out, int out_size)
{
    const float* x       = (const float*)d_in[0];
    const float* W       = (const float*)d_in[1];
    const float* b       = (const float*)d_in[2];
    const int*   batch32 = (const int*)d_in[3];   // int32 or int64 (detected on device)
    const int N = in_sizes[3];
    (void)n_in; (void)out_size;

    const bool vec_in  = ((((uintptr_t)x) | ((uintptr_t)W)) & 15u) == 0;
    const bool vec_out = (((uintptr_t)d_out) & 15u) == 0;

    if (vec_in)
        gap_pass1<true><<<G_NUM * SPLIT, T_P1>>>(x, W, b, batch32, N);
    else
        gap_pass1<false><<<G_NUM * SPLIT, T_P1>>>(x, W, b, batch32, N);

    if (vec_out)
        gap_pass2<true><<<G_NUM, 128>>>((float*)d_out);
    else
        gap_pass2<false><<<G_NUM, 128>>>((float*)d_out);
}